// round 1
// baseline (speedup 1.0000x reference)
#include <cuda_runtime.h>
#include <cuda_bf16.h>
#include <math.h>

// ---------------- problem constants ----------------
#define NN   768
#define FF   64
#define VV   16
#define NB   8
#define HR   64
#define TT   2
#define ROS  32
#define ROV  16
#define PP   176          // F + V + F + V + V
#define AVGI (1.0f/767.0f)

#define TILE   128
#define BLOCKE 384
#define HP   68           // pitch for H   (float4-aligned, low smem conflicts)
#define ESP  68           // pitch for es
#define EVP  52           // pitch for ev (48 used)

#define SMEM_FLOATS (TILE*HP + TILE*ESP + TILE*EVP + TILE*4 + 512 + 64)
#define SMEM_BYTES  (SMEM_FLOATS*4)

// ---------------- device scratch ----------------
__device__ float g_hsnode[NN*FF];     // node scalar state h_s
__device__ float g_hvnode[NN*VV*3];   // node vector state h_v
__device__ float g_hs[NN*FF];         // transformed es source
__device__ float g_hv[NN*VV*3];       // transformed ev source
__device__ float g_aggs[NN*80];       // agg_s
__device__ float g_aggv[NN*96*3];     // agg_v
__device__ float g_com[3];

// ---------------- init ----------------
__global__ void fill_init(const float* __restrict__ embed) {
    int i = blockIdx.x*blockDim.x + threadIdx.x;
    if (i < NN*FF) g_hsnode[i] = embed[i & 63];
    if (i < NN*VV*3) g_hvnode[i] = 0.f;
}

__global__ void com_kernel(const float* __restrict__ x) {
    __shared__ float s0[24], s1[24], s2[24];
    int i = threadIdx.x;           // 768 threads
    float v0 = x[i*3+0], v1 = x[i*3+1], v2 = x[i*3+2];
    #pragma unroll
    for (int o = 16; o > 0; o >>= 1) {
        v0 += __shfl_down_sync(0xffffffffu, v0, o);
        v1 += __shfl_down_sync(0xffffffffu, v1, o);
        v2 += __shfl_down_sync(0xffffffffu, v2, o);
    }
    if ((i & 31) == 0) { s0[i>>5]=v0; s1[i>>5]=v1; s2[i>>5]=v2; }
    __syncthreads();
    if (i == 0) {
        float a0=0,a1=0,a2=0;
        for (int w = 0; w < 24; w++) { a0+=s0[w]; a1+=s1[w]; a2+=s2[w]; }
        g_com[0]=a0/768.f; g_com[1]=a1/768.f; g_com[2]=a2/768.f;
    }
}

// ---------------- node transform: hs = h_s @ Wns ; hv = einsum(h_v, Wnv) ----------------
__global__ void node_transform(const float* __restrict__ wns,
                               const float* __restrict__ wnv) {
    int n = blockIdx.x, f = threadIdx.x;   // 64 threads
    __shared__ float sh[64], sv[48];
    sh[f] = g_hsnode[n*64 + f];
    if (f < 48) sv[f] = g_hvnode[n*48 + f];
    __syncthreads();
    float acc = 0.f;
    #pragma unroll
    for (int k = 0; k < 64; k++) acc = fmaf(sh[k], wns[k*64 + f], acc);
    g_hs[n*64 + f] = acc;
    if (f < 48) {
        int w = f/3, c = f - w*3;
        float a = 0.f;
        #pragma unroll
        for (int v = 0; v < 16; v++) a = fmaf(sv[v*3 + c], wnv[v*16 + w], a);
        g_hv[n*48 + f] = a;
    }
}

// ---------------- the big one: per-receiver edge aggregation ----------------
__global__ __launch_bounds__(BLOCKE, 1)
void edge_kernel(const float* __restrict__ x,
                 const float* __restrict__ w1, const float* __restrict__ b1,
                 const float* __restrict__ w2, int has_v) {
    extern __shared__ float sm[];
    float* sH  = sm;                       // [TILE][HP]
    float* sES = sH  + TILE*HP;            // [TILE][ESP]
    float* sEV = sES + TILE*ESP;           // [TILE][EVP]
    float* sRH = sEV + TILE*EVP;           // [TILE][4]
    float* sW1 = sRH + TILE*4;             // [8][64]
    float* sB1 = sW1 + 512;                // [64]

    const int tid = threadIdx.x;
    const int rcv = blockIdx.x;

    for (int i = tid; i < 512; i += BLOCKE) sW1[i] = w1[i];
    if (tid < 64) sB1[tid] = b1[tid];

    const float xr0 = x[rcv*3+0], xr1 = x[rcv*3+1], xr2 = x[rcv*3+2];

    const bool act = tid < 352;
    const int half = (tid >= 176) ? 1 : 0;
    const int p = act ? (tid - half*176) : 0;
    int cls, idx0;
    if      (p < 64)  { cls = 0; idx0 = p; }
    else if (p < 80)  { cls = 1; idx0 = p - 64; }
    else if (p < 144) { cls = 2; idx0 = p - 80; }
    else if (p < 160) { cls = 3; idx0 = p - 144; }
    else              { cls = 4; idx0 = p - 160; }
    const bool compute = act && (has_v || cls == 0 || cls == 2);

    float wcol[64];
    if (act) {
        #pragma unroll
        for (int h = 0; h < 64; h++) wcol[h] = w2[h*PP + p];
    }
    float a0 = 0.f, a1 = 0.f, a2 = 0.f;

    for (int t0 = 0; t0 < NN; t0 += TILE) {
        __syncthreads();   // smem from previous tile no longer needed
        // stage es (and ev) cooperatively, coalesced
        for (int i = tid; i < TILE*64; i += BLOCKE) {
            int e = i >> 6, f = i & 63;
            sES[e*ESP + f] = g_hs[(t0 + e)*64 + f];
        }
        if (has_v) {
            for (int i = tid; i < TILE*48; i += BLOCKE) {
                int e = i / 48, s2i = i - e*48;
                sEV[e*EVP + s2i] = g_hv[(t0 + e)*48 + s2i];
            }
        }
        // phase 1: geometry + radial hidden layer
        if (tid < TILE) {
            const int s = t0 + tid;
            const float vx = xr0 - x[s*3+0];
            const float vy = xr1 - x[s*3+1];
            const float vz = xr2 - x[s*3+2];
            const float d2 = vx*vx + vy*vy + vz*vz;
            const float rr = sqrtf(d2);
            const bool self = (s == rcv);
            const float rinv = self ? 0.f : (1.f / rr);
            sRH[tid*4+0] = vx*rinv;
            sRH[tid*4+1] = vy*rinv;
            sRH[tid*4+2] = vz*rinv;
            const float rg = self ? 1.f : rr;
            float sa, ca;
            __sincosf(0.31415926535f * rg, &sa, &ca);   // pi/RMAX
            const float coef = 0.4472135955f * rinv;    // sqrt(2/RMAX)/r
            float rb[8];
            {
                float sp = 0.f, sc = sa;
                const float twoc = 2.f*ca;
                #pragma unroll
                for (int nb = 0; nb < 8; nb++) {
                    rb[nb] = sc * coef;
                    float sn = fmaf(twoc, sc, -sp);
                    sp = sc; sc = sn;
                }
            }
            const float u = 2.f * (1.f - rr*0.1f);
            const float env = (!self && u > 0.f) ? 1.2f*__expf(-1.f/u) : 0.f;
            #pragma unroll
            for (int h = 0; h < 64; h++) {
                float t = sB1[h];
                #pragma unroll
                for (int nb = 0; nb < 8; nb++) t = fmaf(rb[nb], sW1[nb*64 + h], t);
                const float sg = 1.f / (1.f + __expf(-t));
                sH[tid*HP + h] = env * t * sg;   // env folded into H (linear wrt W2)
            }
        }
        __syncthreads();
        // phase 2: R = H @ W2 column p, message-form, accumulate in registers
        if (compute) {
            const int ebeg = half*64;
            for (int e = ebeg; e < ebeg + 64; e++) {
                const float* He = &sH[e*HP];
                float q0 = 0.f, q1 = 0.f;
                #pragma unroll
                for (int h = 0; h < 64; h += 8) {
                    float4 A = *(const float4*)(He + h);
                    float4 B = *(const float4*)(He + h + 4);
                    q0 = fmaf(A.x, wcol[h+0], q0); q1 = fmaf(A.y, wcol[h+1], q1);
                    q0 = fmaf(A.z, wcol[h+2], q0); q1 = fmaf(A.w, wcol[h+3], q1);
                    q0 = fmaf(B.x, wcol[h+4], q0); q1 = fmaf(B.y, wcol[h+5], q1);
                    q0 = fmaf(B.z, wcol[h+6], q0); q1 = fmaf(B.w, wcol[h+7], q1);
                }
                const float R = q0 + q1;
                if (cls == 0) {
                    a0 = fmaf(sES[e*ESP + idx0], R, a0);
                } else if (cls == 1) {
                    const float* ev = &sEV[e*EVP + idx0*3];
                    float dot = ev[0]*sRH[e*4+0] + ev[1]*sRH[e*4+1] + ev[2]*sRH[e*4+2];
                    a0 = fmaf(dot, R, a0);
                } else if (cls == 2) {
                    const float t2 = sES[e*ESP + idx0] * R;
                    a0 = fmaf(t2, sRH[e*4+0], a0);
                    a1 = fmaf(t2, sRH[e*4+1], a1);
                    a2 = fmaf(t2, sRH[e*4+2], a2);
                } else if (cls == 3) {
                    const float* ev = &sEV[e*EVP + idx0*3];
                    a0 = fmaf(ev[0], R, a0);
                    a1 = fmaf(ev[1], R, a1);
                    a2 = fmaf(ev[2], R, a2);
                } else {
                    const float* ev = &sEV[e*EVP + idx0*3];
                    const float rx = sRH[e*4+0], ry = sRH[e*4+1], rz = sRH[e*4+2];
                    a0 = fmaf(ev[1]*rz - ev[2]*ry, R, a0);
                    a1 = fmaf(ev[2]*rx - ev[0]*rz, R, a1);
                    a2 = fmaf(ev[0]*ry - ev[1]*rx, R, a2);
                }
            }
        }
    }
    __syncthreads();
    if (act && half == 1) { sH[p*3+0]=a0; sH[p*3+1]=a1; sH[p*3+2]=a2; }
    __syncthreads();
    if (act && half == 0) {
        a0 += sH[p*3+0]; a1 += sH[p*3+1]; a2 += sH[p*3+2];
        if (cls <= 1) {
            g_aggs[rcv*80 + p] = a0 * AVGI;
        } else {
            int row = (cls == 2) ? idx0 : (cls == 3 ? 64 + idx0 : 80 + idx0);
            int base = rcv*288 + row*3;
            g_aggv[base+0] = a0 * AVGI;
            g_aggv[base+1] = a1 * AVGI;
            g_aggv[base+2] = a2 * AVGI;
        }
    }
}

// ---------------- node update ----------------
__global__ void node_update(const float* __restrict__ wmix_s,
                            const float* __restrict__ wmix_v,
                            const float* __restrict__ wgate,
                            const float* __restrict__ wro_s,
                            const float* __restrict__ wro_v,
                            float* __restrict__ out_s,
                            float* __restrict__ out_v,
                            int first, int last) {
    int n = blockIdx.x, t = threadIdx.x;   // 128 threads
    __shared__ float sA[80], sV[288], sM[64], sS[64], sG[16], sMV[48];
    if (t < 80) sA[t] = g_aggs[n*80 + t];
    for (int i = t; i < 288; i += 128) sV[i] = g_aggv[n*288 + i];
    __syncthreads();
    if (t < 64) {
        float m = 0.f;
        #pragma unroll
        for (int p = 0; p < 80; p++) m = fmaf(sA[p], wmix_s[p*64 + t], m);
        sM[t] = m;
        sS[t] = m / (1.f + __expf(-m));
    }
    if (t >= 64 && t < 112) {
        int i = t - 64, v = i/3, c = i - v*3;
        float m = 0.f;
        #pragma unroll
        for (int p = 0; p < 96; p++) m = fmaf(sV[p*3 + c], wmix_v[p*16 + v], m);
        sMV[i] = m;
    }
    __syncthreads();
    if (t < 16) {
        float g = 0.f;
        #pragma unroll
        for (int f = 0; f < 64; f++) g = fmaf(sM[f], wgate[f*16 + t], g);
        sG[t] = 1.f / (1.f + __expf(-g));
    }
    if (t >= 64 && t < 128) g_hsnode[n*64 + (t - 64)] = sS[t - 64];
    __syncthreads();
    if (t < 48) {
        int v = t/3;
        float hv_ = sG[v] * sMV[t];
        g_hvnode[n*48 + t] = hv_;
        sMV[t] = hv_;
    }
    __syncthreads();
    if (t < 32) {
        float o = 0.f;
        #pragma unroll
        for (int f = 0; f < 64; f++) o = fmaf(sS[f], wro_s[f*32 + t], o);
        if (first) out_s[n*32 + t] = o; else out_s[n*32 + t] += o;
    }
    if (t >= 64 && t < 112) {
        int i = t - 64, k = i/3, c = i - k*3;
        float o = 0.f;
        #pragma unroll
        for (int v = 0; v < 16; v++) o = fmaf(sMV[v*3 + c], wro_v[v*16 + k], o);
        float prev = first ? 0.f : out_v[n*48 + i];
        o += prev;
        if (last) o += g_com[c];
        out_v[n*48 + i] = o;
    }
}

// ---------------- launch ----------------
extern "C" void kernel_launch(void* const* d_in, const int* in_sizes, int n_in,
                              void* d_out, int out_size) {
    const float* x      = (const float*)d_in[0];
    const float* embed  = (const float*)d_in[1];
    const float* wns    = (const float*)d_in[2];
    const float* wnv    = (const float*)d_in[3];
    const float* wr1    = (const float*)d_in[4];
    const float* br1    = (const float*)d_in[5];
    const float* wr2    = (const float*)d_in[6];
    const float* wmixs  = (const float*)d_in[7];
    const float* wmixv  = (const float*)d_in[8];
    const float* wgate  = (const float*)d_in[9];
    const float* wros   = (const float*)d_in[10];
    const float* wrov   = (const float*)d_in[11];

    float* out   = (float*)d_out;
    float* out_s = out;                 // [768,32]
    float* out_v = out + NN*ROS;        // [768,16,3]

    cudaFuncSetAttribute(edge_kernel,
        cudaFuncAttributeMaxDynamicSharedMemorySize, SMEM_BYTES);

    fill_init<<<(NN*FF + 255)/256, 256>>>(embed);
    com_kernel<<<1, NN>>>(x);

    for (int t = 0; t < TT; t++) {
        node_transform<<<NN, 64>>>(wns + t*FF*FF, wnv + t*VV*VV);
        edge_kernel<<<NN, BLOCKE, SMEM_BYTES>>>(
            x, wr1 + t*NB*HR, br1 + t*HR, wr2 + t*HR*PP, (t == 0) ? 0 : 1);
        node_update<<<NN, 128>>>(
            wmixs + t*80*64, wmixv + t*96*16, wgate + t*64*16,
            wros + t*64*32, wrov + t*16*16,
            out_s, out_v, (t == 0) ? 1 : 0, (t == TT-1) ? 1 : 0);
    }
}

// round 2
// speedup vs baseline: 1.2757x; 1.2757x over previous
#include <cuda_runtime.h>
#include <cuda_bf16.h>
#include <math.h>

// ---------------- problem constants ----------------
#define NN   768
#define FF   64
#define VV   16
#define NB   8
#define HR   64
#define TT   2
#define ROS  32
#define ROV  16
#define PP   176          // F + V + F + V + V
#define AVGI (1.0f/767.0f)

#define TILE   128
#define BLOCKE 384
#define HP   68           // pitch for H   (16B-aligned rows)
#define ESP  68           // pitch for es
#define EVP  52           // pitch for ev (48 used)

#define SMEM_FLOATS (TILE*HP + TILE*ESP + TILE*EVP + TILE*4 + 512 + 64)
#define SMEM_BYTES  (SMEM_FLOATS*4)

typedef unsigned long long u64;

// ---------------- packed f32x2 helpers (Blackwell) ----------------
__device__ __forceinline__ u64 pack2(float lo, float hi) {
    u64 r; asm("mov.b64 %0,{%1,%2};" : "=l"(r) : "f"(lo), "f"(hi)); return r;
}
__device__ __forceinline__ void unpack2(u64 v, float& lo, float& hi) {
    asm("mov.b64 {%0,%1},%2;" : "=f"(lo), "=f"(hi) : "l"(v));
}
__device__ __forceinline__ u64 fma2(u64 a, u64 b, u64 c) {
    u64 d; asm("fma.rn.f32x2 %0,%1,%2,%3;" : "=l"(d) : "l"(a), "l"(b), "l"(c)); return d;
}

// ---------------- device scratch ----------------
__device__ float g_hsnode[NN*FF];
__device__ float g_hvnode[NN*VV*3];
__device__ float g_hs[NN*FF];
__device__ float g_hv[NN*VV*3];
__device__ float g_aggsH[2][NN*80];
__device__ float g_aggvH[2][NN*288];
__device__ float g_com[3];

// ---------------- init ----------------
__global__ void fill_init(const float* __restrict__ embed) {
    int i = blockIdx.x*blockDim.x + threadIdx.x;
    if (i < NN*FF) g_hsnode[i] = embed[i & 63];
    if (i < NN*VV*3) g_hvnode[i] = 0.f;
}

__global__ void com_kernel(const float* __restrict__ x) {
    __shared__ float s0[24], s1[24], s2[24];
    int i = threadIdx.x;           // 768 threads
    float v0 = x[i*3+0], v1 = x[i*3+1], v2 = x[i*3+2];
    #pragma unroll
    for (int o = 16; o > 0; o >>= 1) {
        v0 += __shfl_down_sync(0xffffffffu, v0, o);
        v1 += __shfl_down_sync(0xffffffffu, v1, o);
        v2 += __shfl_down_sync(0xffffffffu, v2, o);
    }
    if ((i & 31) == 0) { s0[i>>5]=v0; s1[i>>5]=v1; s2[i>>5]=v2; }
    __syncthreads();
    if (i == 0) {
        float a0=0,a1=0,a2=0;
        for (int w = 0; w < 24; w++) { a0+=s0[w]; a1+=s1[w]; a2+=s2[w]; }
        g_com[0]=a0/768.f; g_com[1]=a1/768.f; g_com[2]=a2/768.f;
    }
}

// ---------------- node transform ----------------
__global__ void node_transform(const float* __restrict__ wns,
                               const float* __restrict__ wnv) {
    int n = blockIdx.x, f = threadIdx.x;   // 64 threads
    __shared__ float sh[64], sv[48];
    sh[f] = g_hsnode[n*64 + f];
    if (f < 48) sv[f] = g_hvnode[n*48 + f];
    __syncthreads();
    float acc = 0.f;
    #pragma unroll
    for (int k = 0; k < 64; k++) acc = fmaf(sh[k], wns[k*64 + f], acc);
    g_hs[n*64 + f] = acc;
    if (f < 48) {
        int w = f/3, c = f - w*3;
        float a = 0.f;
        #pragma unroll
        for (int v = 0; v < 16; v++) a = fmaf(sv[v*3 + c], wnv[v*16 + w], a);
        g_hv[n*48 + f] = a;
    }
}

// ---------------- edge aggregation: grid = 2*NN (receiver, sender-half) ----------------
__global__ __launch_bounds__(BLOCKE, 1)
void edge_kernel(const float* __restrict__ x,
                 const float* __restrict__ w1, const float* __restrict__ b1,
                 const float* __restrict__ w2, int has_v) {
    extern __shared__ float sm[];
    float* sH  = sm;                       // [TILE][HP]
    float* sES = sH  + TILE*HP;            // [TILE][ESP]
    float* sEV = sES + TILE*ESP;           // [TILE][EVP]
    float* sRH = sEV + TILE*EVP;           // [TILE][4]
    float* sW1 = sRH + TILE*4;             // [8][64]
    float* sB1 = sW1 + 512;                // [64]

    const int tid = threadIdx.x;
    const int rcv = blockIdx.x >> 1;
    const int bh  = blockIdx.x & 1;        // sender half

    for (int i = tid; i < 512; i += BLOCKE) sW1[i] = w1[i];
    if (tid < 64) sB1[tid] = b1[tid];

    const float xr0 = x[rcv*3+0], xr1 = x[rcv*3+1], xr2 = x[rcv*3+2];

    const bool act = tid < 352;
    const int ph = (tid >= 176) ? 1 : 0;   // p-duplication half (edge sub-range)
    const int p = act ? (tid - ph*176) : 0;
    int cls, idx0;
    if      (p < 64)  { cls = 0; idx0 = p; }
    else if (p < 80)  { cls = 1; idx0 = p - 64; }
    else if (p < 144) { cls = 2; idx0 = p - 80; }
    else if (p < 160) { cls = 3; idx0 = p - 144; }
    else              { cls = 4; idx0 = p - 160; }
    const bool compute = act && (has_v || cls == 0 || cls == 2);

    u64 wcol2[32];
    if (act) {
        #pragma unroll
        for (int j = 0; j < 32; j++)
            wcol2[j] = pack2(w2[(2*j)*PP + p], w2[(2*j+1)*PP + p]);
    }
    float a0 = 0.f, a1 = 0.f, a2 = 0.f;

    const int t0beg = bh * 384;
    for (int t0 = t0beg; t0 < t0beg + 384; t0 += TILE) {
        __syncthreads();   // previous-tile smem reads done
        // stage es / ev (float4 coalesced)
        for (int i = tid; i < TILE*16; i += BLOCKE) {
            int e = i >> 4, f4 = i & 15;
            ((float4*)&sES[e*ESP])[f4] = ((const float4*)&g_hs[(t0+e)*64])[f4];
        }
        if (has_v) {
            for (int i = tid; i < TILE*12; i += BLOCKE) {
                int e = i / 12, f4 = i - e*12;
                ((float4*)&sEV[e*EVP])[f4] = ((const float4*)&g_hv[(t0+e)*48])[f4];
            }
        }
        // ---- phase 1: all 384 threads; edge = tid&127, h-group = tid>>7 ----
        {
            const int e  = tid & 127;
            const int g  = tid >> 7;        // 0..2
            const int s  = t0 + e;
            const float vx = xr0 - x[s*3+0];
            const float vy = xr1 - x[s*3+1];
            const float vz = xr2 - x[s*3+2];
            const float rr = sqrtf(vx*vx + vy*vy + vz*vz);
            const bool self = (s == rcv);
            const float rinv = self ? 0.f : (1.f / rr);
            if (g == 0) {
                sRH[e*4+0] = vx*rinv;
                sRH[e*4+1] = vy*rinv;
                sRH[e*4+2] = vz*rinv;
            }
            const float rg = self ? 1.f : rr;
            float sa, ca;
            __sincosf(0.31415926535f * rg, &sa, &ca);   // pi/RMAX
            const float coef = 0.4472135955f * rinv;    // sqrt(2/RMAX)/r
            u64 rbp[8];
            {
                float sp = 0.f, sc = sa;
                const float twoc = 2.f*ca;
                #pragma unroll
                for (int nb = 0; nb < 8; nb++) {
                    float rb = sc * coef;
                    rbp[nb] = pack2(rb, rb);
                    float sn = fmaf(twoc, sc, -sp);
                    sp = sc; sc = sn;
                }
            }
            const float u = 2.f * (1.f - rr*0.1f);
            const float env = (!self && u > 0.f) ? 1.2f*__expf(-1.f/u) : 0.f;
            const int hb = (g == 0) ? 0 : ((g == 1) ? 22 : 44);
            const int npair = (g == 2) ? 10 : 11;
            const u64* W1p = (const u64*)sW1;
            const u64* B1p = (const u64*)sB1;
            #pragma unroll
            for (int k = 0; k < 11; k++) {
                if (k < npair) {
                    const int h = hb + 2*k;
                    u64 t2 = B1p[h >> 1];
                    #pragma unroll
                    for (int nb = 0; nb < 8; nb++)
                        t2 = fma2(rbp[nb], W1p[(nb*64 + h) >> 1], t2);
                    float ta, tb; unpack2(t2, ta, tb);
                    const float h0 = env * __fdividef(ta, 1.f + __expf(-ta));
                    const float h1 = env * __fdividef(tb, 1.f + __expf(-tb));
                    *(float2*)&sH[e*HP + h] = make_float2(h0, h1);
                }
            }
        }
        __syncthreads();
        // ---- phase 2: R = H @ W2 col p via packed f32x2, message accumulation ----
        if (compute) {
            const int ebeg = ph * 64;
            for (int e8 = 0; e8 < 64; e8++) {
                const int e = ebeg + e8;
                const u64* He = (const u64*)&sH[e*HP];
                u64 q0 = 0ull, q1 = 0ull, q2 = 0ull, q3 = 0ull;
                #pragma unroll
                for (int j = 0; j < 32; j += 4) {
                    ulonglong2 A = *(const ulonglong2*)(He + j);
                    ulonglong2 B = *(const ulonglong2*)(He + j + 2);
                    q0 = fma2(A.x, wcol2[j+0], q0);
                    q1 = fma2(A.y, wcol2[j+1], q1);
                    q2 = fma2(B.x, wcol2[j+2], q2);
                    q3 = fma2(B.y, wcol2[j+3], q3);
                }
                float f0,f1,f2,f3,f4,f5,f6,f7;
                unpack2(q0, f0, f1); unpack2(q1, f2, f3);
                unpack2(q2, f4, f5); unpack2(q3, f6, f7);
                const float R = ((f0+f4)+(f1+f5)) + ((f2+f6)+(f3+f7));
                if (cls == 0) {
                    a0 = fmaf(sES[e*ESP + idx0], R, a0);
                } else if (cls == 1) {
                    const float* ev = &sEV[e*EVP + idx0*3];
                    float dot = ev[0]*sRH[e*4+0] + ev[1]*sRH[e*4+1] + ev[2]*sRH[e*4+2];
                    a0 = fmaf(dot, R, a0);
                } else if (cls == 2) {
                    const float t2 = sES[e*ESP + idx0] * R;
                    a0 = fmaf(t2, sRH[e*4+0], a0);
                    a1 = fmaf(t2, sRH[e*4+1], a1);
                    a2 = fmaf(t2, sRH[e*4+2], a2);
                } else if (cls == 3) {
                    const float* ev = &sEV[e*EVP + idx0*3];
                    a0 = fmaf(ev[0], R, a0);
                    a1 = fmaf(ev[1], R, a1);
                    a2 = fmaf(ev[2], R, a2);
                } else {
                    const float* ev = &sEV[e*EVP + idx0*3];
                    const float rx = sRH[e*4+0], ry = sRH[e*4+1], rz = sRH[e*4+2];
                    a0 = fmaf(ev[1]*rz - ev[2]*ry, R, a0);
                    a1 = fmaf(ev[2]*rx - ev[0]*rz, R, a1);
                    a2 = fmaf(ev[0]*ry - ev[1]*rx, R, a2);
                }
            }
        }
    }
    __syncthreads();
    if (act && ph == 1) { sH[p*3+0]=a0; sH[p*3+1]=a1; sH[p*3+2]=a2; }
    __syncthreads();
    if (act && ph == 0) {
        a0 += sH[p*3+0]; a1 += sH[p*3+1]; a2 += sH[p*3+2];
        if (cls <= 1) {
            g_aggsH[bh][rcv*80 + p] = a0 * AVGI;
        } else {
            int row = (cls == 2) ? idx0 : (cls == 3 ? 64 + idx0 : 80 + idx0);
            int base = rcv*288 + row*3;
            g_aggvH[bh][base+0] = a0 * AVGI;
            g_aggvH[bh][base+1] = a1 * AVGI;
            g_aggvH[bh][base+2] = a2 * AVGI;
        }
    }
}

// ---------------- node update ----------------
__global__ void node_update(const float* __restrict__ wmix_s,
                            const float* __restrict__ wmix_v,
                            const float* __restrict__ wgate,
                            const float* __restrict__ wro_s,
                            const float* __restrict__ wro_v,
                            float* __restrict__ out_s,
                            float* __restrict__ out_v,
                            int first, int last) {
    int n = blockIdx.x, t = threadIdx.x;   // 128 threads
    __shared__ float sA[80], sV[288], sM[64], sS[64], sG[16], sMV[48];
    if (t < 80) sA[t] = g_aggsH[0][n*80 + t] + g_aggsH[1][n*80 + t];
    for (int i = t; i < 288; i += 128) sV[i] = g_aggvH[0][n*288 + i] + g_aggvH[1][n*288 + i];
    __syncthreads();
    if (t < 64) {
        float m = 0.f;
        #pragma unroll
        for (int p = 0; p < 80; p++) m = fmaf(sA[p], wmix_s[p*64 + t], m);
        sM[t] = m;
        sS[t] = m / (1.f + __expf(-m));
    }
    if (t >= 64 && t < 112) {
        int i = t - 64, v = i/3, c = i - v*3;
        float m = 0.f;
        #pragma unroll
        for (int p = 0; p < 96; p++) m = fmaf(sV[p*3 + c], wmix_v[p*16 + v], m);
        sMV[i] = m;
    }
    __syncthreads();
    if (t < 16) {
        float g = 0.f;
        #pragma unroll
        for (int f = 0; f < 64; f++) g = fmaf(sM[f], wgate[f*16 + t], g);
        sG[t] = 1.f / (1.f + __expf(-g));
    }
    if (t >= 64 && t < 128) g_hsnode[n*64 + (t - 64)] = sS[t - 64];
    __syncthreads();
    if (t < 48) {
        int v = t/3;
        float hv_ = sG[v] * sMV[t];
        g_hvnode[n*48 + t] = hv_;
        sMV[t] = hv_;
    }
    __syncthreads();
    if (t < 32) {
        float o = 0.f;
        #pragma unroll
        for (int f = 0; f < 64; f++) o = fmaf(sS[f], wro_s[f*32 + t], o);
        if (first) out_s[n*32 + t] = o; else out_s[n*32 + t] += o;
    }
    if (t >= 64 && t < 112) {
        int i = t - 64, k = i/3, c = i - k*3;
        float o = 0.f;
        #pragma unroll
        for (int v = 0; v < 16; v++) o = fmaf(sMV[v*3 + c], wro_v[v*16 + k], o);
        float prev = first ? 0.f : out_v[n*48 + i];
        o += prev;
        if (last) o += g_com[c];
        out_v[n*48 + i] = o;
    }
}

// ---------------- launch ----------------
extern "C" void kernel_launch(void* const* d_in, const int* in_sizes, int n_in,
                              void* d_out, int out_size) {
    const float* x      = (const float*)d_in[0];
    const float* embed  = (const float*)d_in[1];
    const float* wns    = (const float*)d_in[2];
    const float* wnv    = (const float*)d_in[3];
    const float* wr1    = (const float*)d_in[4];
    const float* br1    = (const float*)d_in[5];
    const float* wr2    = (const float*)d_in[6];
    const float* wmixs  = (const float*)d_in[7];
    const float* wmixv  = (const float*)d_in[8];
    const float* wgate  = (const float*)d_in[9];
    const float* wros   = (const float*)d_in[10];
    const float* wrov   = (const float*)d_in[11];

    float* out   = (float*)d_out;
    float* out_s = out;                 // [768,32]
    float* out_v = out + NN*ROS;        // [768,16,3]

    cudaFuncSetAttribute(edge_kernel,
        cudaFuncAttributeMaxDynamicSharedMemorySize, SMEM_BYTES);

    fill_init<<<(NN*FF + 255)/256, 256>>>(embed);
    com_kernel<<<1, NN>>>(x);

    for (int t = 0; t < TT; t++) {
        node_transform<<<NN, 64>>>(wns + t*FF*FF, wnv + t*VV*VV);
        edge_kernel<<<NN*2, BLOCKE, SMEM_BYTES>>>(
            x, wr1 + t*NB*HR, br1 + t*HR, wr2 + t*HR*PP, (t == 0) ? 0 : 1);
        node_update<<<NN, 128>>>(
            wmixs + t*80*64, wmixv + t*96*16, wgate + t*64*16,
            wros + t*64*32, wrov + t*16*16,
            out_s, out_v, (t == 0) ? 1 : 0, (t == TT-1) ? 1 : 0);
    }
}

// round 3
// speedup vs baseline: 1.3906x; 1.0901x over previous
#include <cuda_runtime.h>
#include <cuda_bf16.h>
#include <math.h>

// ---------------- problem constants ----------------
#define NN   768
#define FF   64
#define VV   16
#define NB   8
#define HR   64
#define TT   2
#define ROS  32
#define ROV  16
#define PP   176          // F + V + F + V + V
#define AVGI (1.0f/767.0f)

#define TILE   128
#define BLOCKE 384
#define HP   68           // pitch for H   (16B-aligned rows)
#define ESP  68           // pitch for es
#define EVP  52           // pitch for ev (48 used)

#define SMEM_FLOATS (TILE*HP + TILE*ESP + TILE*EVP + TILE*4 + 512 + 64)
#define SMEM_BYTES  (SMEM_FLOATS*4)

typedef unsigned long long u64;

// ---------------- packed f32x2 helpers (Blackwell) ----------------
__device__ __forceinline__ u64 pack2(float lo, float hi) {
    u64 r; asm("mov.b64 %0,{%1,%2};" : "=l"(r) : "f"(lo), "f"(hi)); return r;
}
__device__ __forceinline__ void unpack2(u64 v, float& lo, float& hi) {
    asm("mov.b64 {%0,%1},%2;" : "=f"(lo), "=f"(hi) : "l"(v));
}
__device__ __forceinline__ u64 fma2(u64 a, u64 b, u64 c) {
    u64 d; asm("fma.rn.f32x2 %0,%1,%2,%3;" : "=l"(d) : "l"(a), "l"(b), "l"(c)); return d;
}

// ---------------- device scratch ----------------
__device__ float g_hsnode[NN*FF];
__device__ float g_hvnode[NN*VV*3];
__device__ float g_hs[NN*FF];
__device__ float g_hv[NN*VV*3];
__device__ float g_aggsH[2][NN*80];
__device__ float g_aggvH[2][NN*288];
__device__ float g_com[3];

// ---------------- init ----------------
__global__ void fill_init(const float* __restrict__ embed) {
    int i = blockIdx.x*blockDim.x + threadIdx.x;
    if (i < NN*FF) g_hsnode[i] = embed[i & 63];
    if (i < NN*VV*3) g_hvnode[i] = 0.f;
}

__global__ void com_kernel(const float* __restrict__ x) {
    __shared__ float s0[24], s1[24], s2[24];
    int i = threadIdx.x;           // 768 threads
    float v0 = x[i*3+0], v1 = x[i*3+1], v2 = x[i*3+2];
    #pragma unroll
    for (int o = 16; o > 0; o >>= 1) {
        v0 += __shfl_down_sync(0xffffffffu, v0, o);
        v1 += __shfl_down_sync(0xffffffffu, v1, o);
        v2 += __shfl_down_sync(0xffffffffu, v2, o);
    }
    if ((i & 31) == 0) { s0[i>>5]=v0; s1[i>>5]=v1; s2[i>>5]=v2; }
    __syncthreads();
    if (i == 0) {
        float a0=0,a1=0,a2=0;
        for (int w = 0; w < 24; w++) { a0+=s0[w]; a1+=s1[w]; a2+=s2[w]; }
        g_com[0]=a0/768.f; g_com[1]=a1/768.f; g_com[2]=a2/768.f;
    }
}

// ---------------- node transform ----------------
__global__ void node_transform(const float* __restrict__ wns,
                               const float* __restrict__ wnv) {
    int n = blockIdx.x, f = threadIdx.x;   // 64 threads
    __shared__ float sh[64], sv[48];
    sh[f] = g_hsnode[n*64 + f];
    if (f < 48) sv[f] = g_hvnode[n*48 + f];
    __syncthreads();
    float acc = 0.f;
    #pragma unroll
    for (int k = 0; k < 64; k++) acc = fmaf(sh[k], wns[k*64 + f], acc);
    g_hs[n*64 + f] = acc;
    if (f < 48) {
        int w = f/3, c = f - w*3;
        float a = 0.f;
        #pragma unroll
        for (int v = 0; v < 16; v++) a = fmaf(sv[v*3 + c], wnv[v*16 + w], a);
        g_hv[n*48 + f] = a;
    }
}

// ---------------- edge aggregation: grid = 2*NN (receiver, sender-half) ----------------
__global__ __launch_bounds__(BLOCKE, 1)
void edge_kernel(const float* __restrict__ x,
                 const float* __restrict__ w1, const float* __restrict__ b1,
                 const float* __restrict__ w2, int has_v) {
    extern __shared__ float sm[];
    float* sH  = sm;                       // [TILE][HP]
    float* sES = sH  + TILE*HP;            // [TILE][ESP]
    float* sEV = sES + TILE*ESP;           // [TILE][EVP]
    float* sRH = sEV + TILE*EVP;           // [TILE][4]
    float* sW1 = sRH + TILE*4;             // [8][64]
    float* sB1 = sW1 + 512;                // [64]

    const int tid = threadIdx.x;
    const int rcv = blockIdx.x >> 1;
    const int bh  = blockIdx.x & 1;        // sender half

    for (int i = tid; i < 512; i += BLOCKE) sW1[i] = w1[i];
    if (tid < 64) sB1[tid] = b1[tid];

    const float xr0 = x[rcv*3+0], xr1 = x[rcv*3+1], xr2 = x[rcv*3+2];

    const bool act = tid < 352;
    const int ph = (tid >= 176) ? 1 : 0;   // edge sub-range half
    const int p = act ? (tid - ph*176) : 0;
    int cls, idx0;
    if      (p < 64)  { cls = 0; idx0 = p; }
    else if (p < 80)  { cls = 1; idx0 = p - 64; }
    else if (p < 144) { cls = 2; idx0 = p - 80; }
    else if (p < 160) { cls = 3; idx0 = p - 144; }
    else              { cls = 4; idx0 = p - 160; }
    const bool compute = act && (has_v || cls == 0 || cls == 2);

    u64 wcol2[32];
    if (act) {
        #pragma unroll
        for (int j = 0; j < 32; j++)
            wcol2[j] = pack2(w2[(2*j)*PP + p], w2[(2*j+1)*PP + p]);
    }
    float a0 = 0.f, a1 = 0.f, a2 = 0.f;

    const int t0beg = bh * 384;
    for (int t0 = t0beg; t0 < t0beg + 384; t0 += TILE) {
        __syncthreads();   // previous-tile smem reads done
        // stage es / ev (float4 coalesced)
        for (int i = tid; i < TILE*16; i += BLOCKE) {
            int e = i >> 4, f4 = i & 15;
            ((float4*)&sES[e*ESP])[f4] = ((const float4*)&g_hs[(t0+e)*64])[f4];
        }
        if (has_v) {
            for (int i = tid; i < TILE*12; i += BLOCKE) {
                int e = i / 12, f4 = i - e*12;
                ((float4*)&sEV[e*EVP])[f4] = ((const float4*)&g_hv[(t0+e)*48])[f4];
            }
        }
        // ---- phase 1: all 384 threads; edge = tid&127, h-group = tid>>7 ----
        {
            const int e  = tid & 127;
            const int g  = tid >> 7;        // 0..2
            const int s  = t0 + e;
            const float vx = xr0 - x[s*3+0];
            const float vy = xr1 - x[s*3+1];
            const float vz = xr2 - x[s*3+2];
            const float rr = sqrtf(vx*vx + vy*vy + vz*vz);
            const bool self = (s == rcv);
            const float rinv = self ? 0.f : (1.f / rr);
            if (g == 0) {
                sRH[e*4+0] = vx*rinv;
                sRH[e*4+1] = vy*rinv;
                sRH[e*4+2] = vz*rinv;
            }
            const float rg = self ? 1.f : rr;
            float sa, ca;
            __sincosf(0.31415926535f * rg, &sa, &ca);   // pi/RMAX
            const float coef = 0.4472135955f * rinv;    // sqrt(2/RMAX)/r
            u64 rbp[8];
            {
                float sp = 0.f, sc = sa;
                const float twoc = 2.f*ca;
                #pragma unroll
                for (int nb = 0; nb < 8; nb++) {
                    float rb = sc * coef;
                    rbp[nb] = pack2(rb, rb);
                    float sn = fmaf(twoc, sc, -sp);
                    sp = sc; sc = sn;
                }
            }
            const float u = 2.f * (1.f - rr*0.1f);
            const float env = (!self && u > 0.f) ? 1.2f*__expf(-1.f/u) : 0.f;
            const int hb = (g == 0) ? 0 : ((g == 1) ? 22 : 44);
            const int npair = (g == 2) ? 10 : 11;
            const u64* W1p = (const u64*)sW1;
            const u64* B1p = (const u64*)sB1;
            #pragma unroll
            for (int k = 0; k < 11; k++) {
                if (k < npair) {
                    const int h = hb + 2*k;
                    u64 t2 = B1p[h >> 1];
                    #pragma unroll
                    for (int nb = 0; nb < 8; nb++)
                        t2 = fma2(rbp[nb], W1p[(nb*64 + h) >> 1], t2);
                    float ta, tb; unpack2(t2, ta, tb);
                    const float h0 = env * __fdividef(ta, 1.f + __expf(-ta));
                    const float h1 = env * __fdividef(tb, 1.f + __expf(-tb));
                    *(float2*)&sH[e*HP + h] = make_float2(h0, h1);
                }
            }
        }
        __syncthreads();
        // ---- phase 2: two edges jointly, small loop body (I$-friendly) ----
        if (compute) {
            const int ebeg = ph * 64;
            #pragma unroll 1
            for (int e8 = 0; e8 < 64; e8 += 2) {
                const int e0 = ebeg + e8;
                const int e1 = e0 + 1;
                const u64* He0 = (const u64*)&sH[e0*HP];
                const u64* He1 = (const u64*)&sH[e1*HP];
                u64 p00 = 0ull, p01 = 0ull, p10 = 0ull, p11 = 0ull;
                #pragma unroll
                for (int j = 0; j < 32; j += 4) {
                    ulonglong2 A0 = *(const ulonglong2*)(He0 + j);
                    ulonglong2 A1 = *(const ulonglong2*)(He1 + j);
                    ulonglong2 B0 = *(const ulonglong2*)(He0 + j + 2);
                    ulonglong2 B1 = *(const ulonglong2*)(He1 + j + 2);
                    p00 = fma2(A0.x, wcol2[j+0], p00);
                    p10 = fma2(A1.x, wcol2[j+0], p10);
                    p01 = fma2(A0.y, wcol2[j+1], p01);
                    p11 = fma2(A1.y, wcol2[j+1], p11);
                    p00 = fma2(B0.x, wcol2[j+2], p00);
                    p10 = fma2(B1.x, wcol2[j+2], p10);
                    p01 = fma2(B0.y, wcol2[j+3], p01);
                    p11 = fma2(B1.y, wcol2[j+3], p11);
                }
                float f0,f1,f2,f3,g0,g1,g2,g3;
                unpack2(p00, f0, f1); unpack2(p01, f2, f3);
                unpack2(p10, g0, g1); unpack2(p11, g2, g3);
                const float R0 = (f0+f1) + (f2+f3);
                const float R1 = (g0+g1) + (g2+g3);
                #pragma unroll
                for (int q = 0; q < 2; q++) {
                    const int e = q ? e1 : e0;
                    const float R = q ? R1 : R0;
                    if (cls == 0) {
                        a0 = fmaf(sES[e*ESP + idx0], R, a0);
                    } else if (cls == 2) {
                        const float4 rh = *(const float4*)&sRH[e*4];
                        const float t2 = sES[e*ESP + idx0] * R;
                        a0 = fmaf(t2, rh.x, a0);
                        a1 = fmaf(t2, rh.y, a1);
                        a2 = fmaf(t2, rh.z, a2);
                    } else if (cls == 1) {
                        const float4 rh = *(const float4*)&sRH[e*4];
                        const float* ev = &sEV[e*EVP + idx0*3];
                        float dot = ev[0]*rh.x + ev[1]*rh.y + ev[2]*rh.z;
                        a0 = fmaf(dot, R, a0);
                    } else if (cls == 3) {
                        const float* ev = &sEV[e*EVP + idx0*3];
                        a0 = fmaf(ev[0], R, a0);
                        a1 = fmaf(ev[1], R, a1);
                        a2 = fmaf(ev[2], R, a2);
                    } else {
                        const float4 rh = *(const float4*)&sRH[e*4];
                        const float* ev = &sEV[e*EVP + idx0*3];
                        a0 = fmaf(ev[1]*rh.z - ev[2]*rh.y, R, a0);
                        a1 = fmaf(ev[2]*rh.x - ev[0]*rh.z, R, a1);
                        a2 = fmaf(ev[0]*rh.y - ev[1]*rh.x, R, a2);
                    }
                }
            }
        }
    }
    __syncthreads();
    if (act && ph == 1) { sH[p*3+0]=a0; sH[p*3+1]=a1; sH[p*3+2]=a2; }
    __syncthreads();
    if (act && ph == 0) {
        a0 += sH[p*3+0]; a1 += sH[p*3+1]; a2 += sH[p*3+2];
        if (cls <= 1) {
            g_aggsH[bh][rcv*80 + p] = a0 * AVGI;
        } else {
            int row = (cls == 2) ? idx0 : (cls == 3 ? 64 + idx0 : 80 + idx0);
            int base = rcv*288 + row*3;
            g_aggvH[bh][base+0] = a0 * AVGI;
            g_aggvH[bh][base+1] = a1 * AVGI;
            g_aggvH[bh][base+2] = a2 * AVGI;
        }
    }
}

// ---------------- node update ----------------
__global__ void node_update(const float* __restrict__ wmix_s,
                            const float* __restrict__ wmix_v,
                            const float* __restrict__ wgate,
                            const float* __restrict__ wro_s,
                            const float* __restrict__ wro_v,
                            float* __restrict__ out_s,
                            float* __restrict__ out_v,
                            int first, int last) {
    int n = blockIdx.x, t = threadIdx.x;   // 128 threads
    __shared__ float sA[80], sV[288], sM[64], sS[64], sG[16], sMV[48];
    if (t < 80) sA[t] = g_aggsH[0][n*80 + t] + g_aggsH[1][n*80 + t];
    for (int i = t; i < 288; i += 128) sV[i] = g_aggvH[0][n*288 + i] + g_aggvH[1][n*288 + i];
    __syncthreads();
    if (t < 64) {
        float m = 0.f;
        #pragma unroll
        for (int p = 0; p < 80; p++) m = fmaf(sA[p], wmix_s[p*64 + t], m);
        sM[t] = m;
        sS[t] = m / (1.f + __expf(-m));
    }
    if (t >= 64 && t < 112) {
        int i = t - 64, v = i/3, c = i - v*3;
        float m = 0.f;
        #pragma unroll
        for (int p = 0; p < 96; p++) m = fmaf(sV[p*3 + c], wmix_v[p*16 + v], m);
        sMV[i] = m;
    }
    __syncthreads();
    if (t < 16) {
        float g = 0.f;
        #pragma unroll
        for (int f = 0; f < 64; f++) g = fmaf(sM[f], wgate[f*16 + t], g);
        sG[t] = 1.f / (1.f + __expf(-g));
    }
    if (t >= 64 && t < 128) g_hsnode[n*64 + (t - 64)] = sS[t - 64];
    __syncthreads();
    if (t < 48) {
        int v = t/3;
        float hv_ = sG[v] * sMV[t];
        g_hvnode[n*48 + t] = hv_;
        sMV[t] = hv_;
    }
    __syncthreads();
    if (t < 32) {
        float o = 0.f;
        #pragma unroll
        for (int f = 0; f < 64; f++) o = fmaf(sS[f], wro_s[f*32 + t], o);
        if (first) out_s[n*32 + t] = o; else out_s[n*32 + t] += o;
    }
    if (t >= 64 && t < 112) {
        int i = t - 64, k = i/3, c = i - k*3;
        float o = 0.f;
        #pragma unroll
        for (int v = 0; v < 16; v++) o = fmaf(sMV[v*3 + c], wro_v[v*16 + k], o);
        float prev = first ? 0.f : out_v[n*48 + i];
        o += prev;
        if (last) o += g_com[c];
        out_v[n*48 + i] = o;
    }
}

// ---------------- launch ----------------
extern "C" void kernel_launch(void* const* d_in, const int* in_sizes, int n_in,
                              void* d_out, int out_size) {
    const float* x      = (const float*)d_in[0];
    const float* embed  = (const float*)d_in[1];
    const float* wns    = (const float*)d_in[2];
    const float* wnv    = (const float*)d_in[3];
    const float* wr1    = (const float*)d_in[4];
    const float* br1    = (const float*)d_in[5];
    const float* wr2    = (const float*)d_in[6];
    const float* wmixs  = (const float*)d_in[7];
    const float* wmixv  = (const float*)d_in[8];
    const float* wgate  = (const float*)d_in[9];
    const float* wros   = (const float*)d_in[10];
    const float* wrov   = (const float*)d_in[11];

    float* out   = (float*)d_out;
    float* out_s = out;                 // [768,32]
    float* out_v = out + NN*ROS;        // [768,16,3]

    cudaFuncSetAttribute(edge_kernel,
        cudaFuncAttributeMaxDynamicSharedMemorySize, SMEM_BYTES);

    fill_init<<<(NN*FF + 255)/256, 256>>>(embed);
    com_kernel<<<1, NN>>>(x);

    for (int t = 0; t < TT; t++) {
        node_transform<<<NN, 64>>>(wns + t*FF*FF, wnv + t*VV*VV);
        edge_kernel<<<NN*2, BLOCKE, SMEM_BYTES>>>(
            x, wr1 + t*NB*HR, br1 + t*HR, wr2 + t*HR*PP, (t == 0) ? 0 : 1);
        node_update<<<NN, 128>>>(
            wmixs + t*80*64, wmixv + t*96*16, wgate + t*64*16,
            wros + t*64*32, wrov + t*16*16,
            out_s, out_v, (t == 0) ? 1 : 0, (t == TT-1) ? 1 : 0);
    }
}